// round 15
// baseline (speedup 1.0000x reference)
#include <cuda_runtime.h>
#include <cuda_bf16.h>

#define NN 100000
#define NE 3200000
#define DD 128
#define NB 98   /* ceil(NN/1024) */
#define NSTAGE 4
#define GEMM_SMEM (3 * NSTAGE * 128 * 24 * 2)  /* A + W1 + W2, bf16 */

// ---------------- scratch (device globals; allocation-free) ----------------
__device__ __nv_bfloat16 g_hb[(size_t)NN * DD];   // bf16 layer input/output
__device__ __nv_bfloat16 g_bt[(size_t)NN * DD];   // bf16 pre-scaled GEMM output u_j = dinv_j * t_j
__device__ __nv_bfloat16 g_w1a[DD * DD], g_w1b[DD * DD];  // w1 split, transposed [n][k]
__device__ __nv_bfloat16 g_w2a[DD * DD], g_w2b[DD * DD];  // w2 split, transposed [n][k]
__device__ float g_dinv[NN];
__device__ float g_s[NN];
__device__ float g_c[NN];
__device__ int   g_cnt[NN];
__device__ int   g_off[NN];
__device__ int   g_cur[NN];
__device__ int   g_csr[NE];
__device__ int   g_bsum[NB];
__device__ int   g_bpre[NB];
__device__ float g_v[DD];

// ---------------- setup: zero + W split + x->bf16 convert ----------------
__global__ void k_zero(const float* __restrict__ w1, const float* __restrict__ w2,
                       const float* __restrict__ x) {
    int i = blockIdx.x * blockDim.x + threadIdx.x;
    if (i < NN) { g_cnt[i] = 0; g_s[i] = 0.0f; }
    if (i < DD) g_v[i] = 0.0f;
    if (i < DD * DD) {
        int k = i >> 7, n = i & 127;
        float a = w1[i];
        __nv_bfloat16 ha = __float2bfloat16_rn(a);
        g_w1a[n * 128 + k] = ha;
        g_w1b[n * 128 + k] = __float2bfloat16_rn(a - __bfloat162float(ha));
        float b = w2[i];
        __nv_bfloat16 hb = __float2bfloat16_rn(b);
        g_w2a[n * 128 + k] = hb;
        g_w2b[n * 128 + k] = __float2bfloat16_rn(b - __bfloat162float(hb));
    }
    // streaming convert x (fp32) -> g_hb (bf16); layer-1 GEMM reads g_hb
    const float4* x4 = (const float4*)x;
    uint2* h4 = (uint2*)g_hb;
    size_t total = (size_t)NN * DD / 4;
    size_t stride = (size_t)gridDim.x * blockDim.x;
    for (size_t p = i; p < total; p += stride) {
        float4 v = x4[p];
        __nv_bfloat162 p0 = __floats2bfloat162_rn(v.x, v.y);
        __nv_bfloat162 p1 = __floats2bfloat162_rn(v.z, v.w);
        h4[p] = make_uint2(*(unsigned*)&p0, *(unsigned*)&p1);
    }
}

__global__ void k_count(const int* __restrict__ ei) {
    int e = blockIdx.x * blockDim.x + threadIdx.x;
    if (e < NE) atomicAdd(&g_cnt[ei[NE + e]], 1);
}

__global__ void k_dinv() {
    int i = blockIdx.x * blockDim.x + threadIdx.x;
    if (i < NN) g_dinv[i] = rsqrtf((float)(g_cnt[i] + 1));
}

__global__ void k_scan1() {
    __shared__ int sm[1024];
    int t = threadIdx.x;
    int i = blockIdx.x * 1024 + t;
    int v = (i < NN) ? g_cnt[i] : 0;
    sm[t] = v;
    __syncthreads();
    for (int off = 1; off < 1024; off <<= 1) {
        int x = (t >= off) ? sm[t - off] : 0;
        __syncthreads();
        sm[t] += x;
        __syncthreads();
    }
    if (i < NN) g_off[i] = sm[t] - v;
    if (t == 1023) g_bsum[blockIdx.x] = sm[1023];
}

__global__ void k_scan2() {
    __shared__ int sm[128];
    int t = threadIdx.x;
    int v = (t < NB) ? g_bsum[t] : 0;
    sm[t] = v;
    __syncthreads();
    for (int off = 1; off < 128; off <<= 1) {
        int x = (t >= off) ? sm[t - off] : 0;
        __syncthreads();
        sm[t] += x;
        __syncthreads();
    }
    if (t < NB) g_bpre[t] = sm[t] - v;
}

__global__ void k_scan3() {
    int i = blockIdx.x * blockDim.x + threadIdx.x;
    if (i < NN) {
        int o = g_off[i] + g_bpre[i >> 10];
        g_off[i] = o;
        g_cur[i] = o;
    }
}

__global__ void k_fill(const int* __restrict__ ei) {
    int e = blockIdx.x * blockDim.x + threadIdx.x;
    if (e >= NE) return;
    int s = ei[e];
    int d = ei[NE + e];
    int p = atomicAdd(&g_cur[d], 1);
    g_csr[p] = s;
    atomicAdd(&g_s[s], g_dinv[d]);
}

__global__ void k_coef() {
    int i = blockIdx.x * blockDim.x + threadIdx.x;
    if (i < NN) {
        float di = g_dinv[i];
        g_c[i] = di * g_s[i] + di * di;
    }
}

// ---------------- ldmatrix / cp.async helpers ----------------
__device__ __forceinline__ void ldsm4(unsigned& r0, unsigned& r1, unsigned& r2,
                                      unsigned& r3, const void* p) {
    unsigned addr = (unsigned)__cvta_generic_to_shared(p);
    asm volatile("ldmatrix.sync.aligned.m8n8.x4.shared.b16 {%0,%1,%2,%3}, [%4];"
                 : "=r"(r0), "=r"(r1), "=r"(r2), "=r"(r3) : "r"(addr));
}
__device__ __forceinline__ void cpa8(void* dst, const void* src) {
    unsigned d = (unsigned)__cvta_generic_to_shared(dst);
    asm volatile("cp.async.ca.shared.global [%0], [%1], 8;" :: "r"(d), "l"(src));
}

// ---------------- GEMM: g_bt[r,:] = bf16( dinv[r] * (A[r,:] @ W) ) ---------
// A = g_hb (bf16; layer-1 input pre-converted in k_zero).
// Split-precision W (bf16 hi+lo, pre-built transposed [n][k] tables; weight
// error ~2^-16). 128x128 block tile, 512 threads = 16 warps, warp m32 x n32.
// 4-stage cp.async pipeline: chunk-k loads issued 3 chunks ahead; wait_group 2
// + one barrier per chunk. Smem rows 24 bf16 (48B): ldsm phases conflict-free.
template <int MODE>
__global__ void __launch_bounds__(512, 2) k_gemm() {
    extern __shared__ __nv_bfloat16 smem[];
    __nv_bfloat16 (*As)[24]  = (__nv_bfloat16(*)[24])smem;                       // [NSTAGE*128][24]
    __nv_bfloat16 (*W1s)[24] = (__nv_bfloat16(*)[24])(smem + NSTAGE * 128 * 24);
    __nv_bfloat16 (*W2s)[24] = (__nv_bfloat16(*)[24])(smem + 2 * NSTAGE * 128 * 24);

    int tid  = threadIdx.x;
    int warp = tid >> 5;
    int lane = tid & 31;
    int grp  = lane >> 2;
    int tig  = lane & 3;
    int m0   = (warp & 3) * 32;
    int n0   = (warp >> 2) * 32;
    int row0 = blockIdx.x * 128;

    int rA = tid >> 2, kq = tid & 3;   // staging role: row/col rA, k-quad kq
    int grA = row0 + rA; if (grA >= NN) grA = NN - 1;

    const __nv_bfloat16* Ab = g_hb;
    const __nv_bfloat16* Wa = MODE ? g_w1a : g_w2a;
    const __nv_bfloat16* Wb = MODE ? g_w1b : g_w2b;

    auto stage = [&](int st, int kc) {
        int kb = kc * 16;
        cpa8(&As[st * 128 + rA][kq * 4],  Ab + (size_t)grA * 128 + kb + kq * 4);
        cpa8(&W1s[st * 128 + rA][kq * 4], Wa + rA * 128 + kb + kq * 4);
        cpa8(&W2s[st * 128 + rA][kq * 4], Wb + rA * 128 + kb + kq * 4);
        asm volatile("cp.async.commit_group;" ::: "memory");
    };

    // prologue: stages 0..2 in flight
    stage(0, 0);
    stage(1, 1);
    stage(2, 2);

    float c[2][4][4];
#pragma unroll
    for (int mi = 0; mi < 2; mi++)
#pragma unroll
        for (int ni = 0; ni < 4; ni++)
#pragma unroll
            for (int j = 0; j < 4; j++) c[mi][ni][j] = 0.0f;

    int lrow  = lane & 15;
    int khalf = (lane >> 4) * 8;   // 8 bf16 = 16B

#pragma unroll
    for (int kc = 0; kc < 8; kc++) {
        asm volatile("cp.async.wait_group 2;" ::: "memory");
        __syncthreads();

        int buf = (kc & 3) * 128;

        unsigned a[2][4];
#pragma unroll
        for (int mi = 0; mi < 2; mi++)
            ldsm4(a[mi][0], a[mi][1], a[mi][2], a[mi][3],
                  &As[buf + m0 + 16 * mi + lrow][khalf]);

#pragma unroll
        for (int h = 0; h < 2; h++) {
            __nv_bfloat16 (*Wp)[24] = h ? W2s : W1s;
            unsigned b[2][4];
#pragma unroll
            for (int nt = 0; nt < 2; nt++)
                ldsm4(b[nt][0], b[nt][1], b[nt][2], b[nt][3],
                      &Wp[buf + n0 + 16 * nt + lrow][khalf]);
#pragma unroll
            for (int ni = 0; ni < 4; ni++) {
                int nt = ni >> 1, par = ni & 1;
                unsigned b0 = b[nt][par];
                unsigned b1 = b[nt][par + 2];
#pragma unroll
                for (int mi = 0; mi < 2; mi++) {
                    asm volatile(
                        "mma.sync.aligned.m16n8k16.row.col.f32.bf16.bf16.f32 "
                        "{%0,%1,%2,%3}, {%4,%5,%6,%7}, {%8,%9}, {%0,%1,%2,%3};"
                        : "+f"(c[mi][ni][0]), "+f"(c[mi][ni][1]),
                          "+f"(c[mi][ni][2]), "+f"(c[mi][ni][3])
                        : "r"(a[mi][0]), "r"(a[mi][1]), "r"(a[mi][2]), "r"(a[mi][3]),
                          "r"(b0), "r"(b1));
                }
            }
        }

        if (kc + 3 < 8) stage((kc + 3) & 3, kc + 3);
    }

    // epilogue: scale rows by dinv, store bf16x2
    __nv_bfloat162* bt2 = (__nv_bfloat162*)g_bt;
#pragma unroll
    for (int mi = 0; mi < 2; mi++) {
#pragma unroll
        for (int h = 0; h < 2; h++) {
            int row = row0 + m0 + 16 * mi + grp + 8 * h;
            if (row < NN) {
                float d = g_dinv[row];
#pragma unroll
                for (int ni = 0; ni < 4; ni++) {
                    bt2[(size_t)row * 64 + n0 / 2 + 4 * ni + tig] =
                        __floats2bfloat162_rn(c[mi][ni][2 * h] * d,
                                              c[mi][ni][2 * h + 1] * d);
                }
            }
        }
    }
}

// ---------------- aggregation: one warp per dst node (bf16 gather) --------
// g_hb[i,:] = relu( dinv_i * ( sum_{j in in(i)} u_j + u_i ) + b )
__device__ __forceinline__ float4 bf4(uint2 u) {
    float2 lo = __bfloat1622float2(*(__nv_bfloat162*)&u.x);
    float2 hi = __bfloat1622float2(*(__nv_bfloat162*)&u.y);
    return make_float4(lo.x, lo.y, hi.x, hi.y);
}

__global__ void __launch_bounds__(256) k_agg(const float* __restrict__ bias, int dorelu) {
    int gw = (blockIdx.x * blockDim.x + threadIdx.x) >> 5;
    int lane = threadIdx.x & 31;
    if (gw >= NN) return;

    const uint2* tv = (const uint2*)g_bt;
    float4 acc = bf4(tv[(size_t)gw * 32 + lane]);   // self term u_i

    int e = g_off[gw];
    int end = e + g_cnt[gw];
    for (; e + 8 <= end; e += 8) {
        int j[8];
#pragma unroll
        for (int t = 0; t < 8; t++) j[t] = g_csr[e + t];
        float4 r[8];
#pragma unroll
        for (int t = 0; t < 8; t++) r[t] = bf4(tv[(size_t)j[t] * 32 + lane]);
#pragma unroll
        for (int t = 0; t < 8; t++) {
            acc.x += r[t].x; acc.y += r[t].y;
            acc.z += r[t].z; acc.w += r[t].w;
        }
    }
    for (; e < end; e++) {
        float4 r = bf4(tv[(size_t)g_csr[e] * 32 + lane]);
        acc.x += r.x; acc.y += r.y; acc.z += r.z; acc.w += r.w;
    }

    float di = g_dinv[gw];
    float4 b = ((const float4*)bias)[lane];
    float ox = di * acc.x + b.x;
    float oy = di * acc.y + b.y;
    float oz = di * acc.z + b.z;
    float ow = di * acc.w + b.w;
    if (dorelu) {
        ox = fmaxf(ox, 0.f); oy = fmaxf(oy, 0.f);
        oz = fmaxf(oz, 0.f); ow = fmaxf(ow, 0.f);
    }
    __nv_bfloat162 p0 = __floats2bfloat162_rn(ox, oy);
    __nv_bfloat162 p1 = __floats2bfloat162_rn(oz, ow);
    uint2 packed = make_uint2(*(unsigned*)&p0, *(unsigned*)&p1);
    ((uint2*)g_hb)[(size_t)gw * 32 + lane] = packed;
}

// ---------------- final reduction: g_v = sum_i c_i * h2_i -----------------
__global__ void __launch_bounds__(128) k_reduce() {
    int c = threadIdx.x;
    float acc = 0.0f;
    for (int i = blockIdx.x; i < NN; i += gridDim.x)
        acc += g_c[i] * __bfloat162float(g_hb[(size_t)i * 128 + c]);
    atomicAdd(&g_v[c], acc);
}

__global__ void __launch_bounds__(128) k_final(const float* __restrict__ w3,
                                               const float* __restrict__ b3,
                                               float* __restrict__ out) {
    __shared__ float sv[128];
    int t = threadIdx.x;
    sv[t] = g_v[t];
    __syncthreads();
    float acc = 0.0f;
#pragma unroll 8
    for (int d = 0; d < 128; d++) acc += sv[d] * w3[d * 128 + t];
    out[t] = acc * (1.0f / (float)NN) + b3[t];
}

// ---------------- launch ----------------
extern "C" void kernel_launch(void* const* d_in, const int* in_sizes, int n_in,
                              void* d_out, int out_size) {
    const float* x  = (const float*)d_in[0];
    const int*   ei = (const int*)d_in[1];
    const float* w1 = (const float*)d_in[2];
    const float* b1 = (const float*)d_in[3];
    const float* w2 = (const float*)d_in[4];
    const float* b2 = (const float*)d_in[5];
    const float* w3 = (const float*)d_in[6];
    const float* b3 = (const float*)d_in[7];
    float* out = (float*)d_out;

    cudaFuncSetAttribute(k_gemm<1>, cudaFuncAttributeMaxDynamicSharedMemorySize,
                         GEMM_SMEM);
    cudaFuncSetAttribute(k_gemm<0>, cudaFuncAttributeMaxDynamicSharedMemorySize,
                         GEMM_SMEM);

    int nThreads = 256;
    int gN = (NN + nThreads - 1) / nThreads;
    int gE = (NE + nThreads - 1) / nThreads;
    int gGemm = (NN + 127) / 128;
    int gAgg = (NN * 32 + nThreads - 1) / nThreads;

    k_zero<<<gN, nThreads>>>(w1, w2, x);
    k_count<<<gE, nThreads>>>(ei);
    k_dinv<<<gN, nThreads>>>();
    // layer-1 GEMM kept in the ncu captured-launch slot (4th launch).
    k_gemm<1><<<gGemm, 512, GEMM_SMEM>>>();
    k_scan1<<<NB, 1024>>>();
    k_scan2<<<1, 128>>>();
    k_scan3<<<gN, nThreads>>>();
    k_fill<<<gE, nThreads>>>(ei);
    k_coef<<<gN, nThreads>>>();

    k_agg<<<gAgg, 256>>>(b1, 1);
    // layer 2
    k_gemm<0><<<gGemm, 512, GEMM_SMEM>>>();
    k_agg<<<gAgg, 256>>>(b2, 1);
    // layer 3 collapsed: out = ((sum_i c_i h2_i) @ w3)/N + b3
    k_reduce<<<512, 128>>>();
    k_final<<<1, 128>>>(w3, b3, out);
}

// round 17
// speedup vs baseline: 1.0907x; 1.0907x over previous
#include <cuda_runtime.h>
#include <cuda_bf16.h>

#define NN 100000
#define NE 3200000
#define DD 128
#define NB 98   /* ceil(NN/1024) */

// ---------------- scratch (device globals; allocation-free) ----------------
__device__ __nv_bfloat16 g_hb[(size_t)NN * DD];   // bf16 layer input/output
__device__ __nv_bfloat16 g_bt[(size_t)NN * DD];   // bf16 pre-scaled GEMM output u_j = dinv_j * t_j
__device__ __nv_bfloat16 g_w1a[DD * DD], g_w1b[DD * DD];  // w1 split, transposed [n][k]
__device__ __nv_bfloat16 g_w2a[DD * DD], g_w2b[DD * DD];  // w2 split, transposed [n][k]
__device__ float g_dinv[NN];
__device__ float g_s[NN];
__device__ float g_c[NN];
__device__ int   g_cnt[NN];
__device__ int   g_off[NN];
__device__ int   g_cur[NN];
__device__ int   g_csr[NE];
__device__ int   g_bsum[NB];
__device__ int   g_bpre[NB];
__device__ float g_v[DD];

// ---------------- setup kernels ----------------
// zero graph-side scratch (main stream)
__global__ void k_zero() {
    int i = blockIdx.x * blockDim.x + threadIdx.x;
    if (i < NN) { g_cnt[i] = 0; g_s[i] = 0.0f; }
    if (i < DD) g_v[i] = 0.0f;
}

// W split + x->bf16 convert (side stream; independent of graph build)
__global__ void k_prep(const float* __restrict__ w1, const float* __restrict__ w2,
                       const float* __restrict__ x) {
    int i = blockIdx.x * blockDim.x + threadIdx.x;
    if (i < DD * DD) {
        int k = i >> 7, n = i & 127;
        float a = w1[i];
        __nv_bfloat16 ha = __float2bfloat16_rn(a);
        g_w1a[n * 128 + k] = ha;
        g_w1b[n * 128 + k] = __float2bfloat16_rn(a - __bfloat162float(ha));
        float b = w2[i];
        __nv_bfloat16 hb = __float2bfloat16_rn(b);
        g_w2a[n * 128 + k] = hb;
        g_w2b[n * 128 + k] = __float2bfloat16_rn(b - __bfloat162float(hb));
    }
    const float4* x4 = (const float4*)x;
    uint2* h4 = (uint2*)g_hb;
    size_t total = (size_t)NN * DD / 4;
    size_t stride = (size_t)gridDim.x * blockDim.x;
    for (size_t p = i; p < total; p += stride) {
        float4 v = x4[p];
        __nv_bfloat162 p0 = __floats2bfloat162_rn(v.x, v.y);
        __nv_bfloat162 p1 = __floats2bfloat162_rn(v.z, v.w);
        h4[p] = make_uint2(*(unsigned*)&p0, *(unsigned*)&p1);
    }
}

__global__ void k_count(const int* __restrict__ ei) {
    int e = blockIdx.x * blockDim.x + threadIdx.x;
    if (e < NE) atomicAdd(&g_cnt[ei[NE + e]], 1);
}

__global__ void k_dinv() {
    int i = blockIdx.x * blockDim.x + threadIdx.x;
    if (i < NN) g_dinv[i] = rsqrtf((float)(g_cnt[i] + 1));
}

__global__ void k_scan1() {
    __shared__ int sm[1024];
    int t = threadIdx.x;
    int i = blockIdx.x * 1024 + t;
    int v = (i < NN) ? g_cnt[i] : 0;
    sm[t] = v;
    __syncthreads();
    for (int off = 1; off < 1024; off <<= 1) {
        int x = (t >= off) ? sm[t - off] : 0;
        __syncthreads();
        sm[t] += x;
        __syncthreads();
    }
    if (i < NN) g_off[i] = sm[t] - v;
    if (t == 1023) g_bsum[blockIdx.x] = sm[1023];
}

__global__ void k_scan2() {
    __shared__ int sm[128];
    int t = threadIdx.x;
    int v = (t < NB) ? g_bsum[t] : 0;
    sm[t] = v;
    __syncthreads();
    for (int off = 1; off < 128; off <<= 1) {
        int x = (t >= off) ? sm[t - off] : 0;
        __syncthreads();
        sm[t] += x;
        __syncthreads();
    }
    if (t < NB) g_bpre[t] = sm[t] - v;
}

__global__ void k_scan3() {
    int i = blockIdx.x * blockDim.x + threadIdx.x;
    if (i < NN) {
        int o = g_off[i] + g_bpre[i >> 10];
        g_off[i] = o;
        g_cur[i] = o;
    }
}

__global__ void k_fill(const int* __restrict__ ei) {
    int e = blockIdx.x * blockDim.x + threadIdx.x;
    if (e >= NE) return;
    int s = ei[e];
    int d = ei[NE + e];
    int p = atomicAdd(&g_cur[d], 1);
    g_csr[p] = s;
    atomicAdd(&g_s[s], g_dinv[d]);
}

__global__ void k_coef() {
    int i = blockIdx.x * blockDim.x + threadIdx.x;
    if (i < NN) {
        float di = g_dinv[i];
        g_c[i] = di * g_s[i] + di * di;
    }
}

// ---------------- ldmatrix helper ----------------
__device__ __forceinline__ void ldsm4(unsigned& r0, unsigned& r1, unsigned& r2,
                                      unsigned& r3, const void* p) {
    unsigned addr = (unsigned)__cvta_generic_to_shared(p);
    asm volatile("ldmatrix.sync.aligned.m8n8.x4.shared.b16 {%0,%1,%2,%3}, [%4];"
                 : "=r"(r0), "=r"(r1), "=r"(r2), "=r"(r3) : "r"(addr));
}

// ---------------- GEMM: g_bt[r,:] = bf16( dinv[r] * (A[r,:] @ W) ) ---------
// A = g_hb (bf16; x pre-converted in k_prep). W = pre-split transposed bf16
// tables (hi+lo; weight error ~2^-16), accumulated into the same fp32 accums.
// 128x128 block tile, 512 threads = 16 warps, warp tile m32 x n32.
// Double-buffered k16 chunks; smem rows 24 bf16 (48B): ldsm phases hit
// distinct banks. (R12 configuration: best measured, 41.9us.)
// MODE selects the weight tables only.
template <int MODE>
__global__ void __launch_bounds__(512, 2) k_gemm() {
    __shared__ alignas(16) __nv_bfloat16 As[2][128][24];
    __shared__ alignas(16) __nv_bfloat16 W1s[2][128][24];
    __shared__ alignas(16) __nv_bfloat16 W2s[2][128][24];

    int tid  = threadIdx.x;
    int warp = tid >> 5;
    int lane = tid & 31;
    int grp  = lane >> 2;   // 0..7
    int tig  = lane & 3;    // 0..3
    int m0   = (warp & 3) * 32;
    int n0   = (warp >> 2) * 32;
    int row0 = blockIdx.x * 128;

    float c[2][4][4];
#pragma unroll
    for (int mi = 0; mi < 2; mi++)
#pragma unroll
        for (int ni = 0; ni < 4; ni++)
#pragma unroll
            for (int j = 0; j < 4; j++) c[mi][ni][j] = 0.0f;

    // staging roles: one uint2 (4 bf16) per thread per array
    int mA = tid >> 2, kq = tid & 3;
    int grA = row0 + mA; if (grA >= NN) grA = NN - 1;

    const __nv_bfloat16* Ab = g_hb;
    const __nv_bfloat16* Wa = MODE ? g_w1a : g_w2a;
    const __nv_bfloat16* Wb = MODE ? g_w1b : g_w2b;

    auto stageA = [&](int buf, int kb) {
        *(uint2*)&As[buf][mA][kq * 4] =
            *(const uint2*)&Ab[(size_t)grA * 128 + kb + kq * 4];
    };
    auto stageW = [&](int buf, int kb) {
        *(uint2*)&W1s[buf][mA][kq * 4] = *(const uint2*)&Wa[mA * 128 + kb + kq * 4];
        *(uint2*)&W2s[buf][mA][kq * 4] = *(const uint2*)&Wb[mA * 128 + kb + kq * 4];
    };

    stageA(0, 0);
    stageW(0, 0);
    __syncthreads();

    int lrow  = lane & 15;
    int khalf = (lane >> 4) * 8;   // 8 bf16 = 16B

    for (int kc = 0; kc < 8; kc++) {
        int buf = kc & 1;

        if (kc < 7) {
            stageA(buf ^ 1, (kc + 1) * 16);
            stageW(buf ^ 1, (kc + 1) * 16);
        }

        unsigned a[2][4];
#pragma unroll
        for (int mi = 0; mi < 2; mi++)
            ldsm4(a[mi][0], a[mi][1], a[mi][2], a[mi][3],
                  &As[buf][m0 + 16 * mi + lrow][khalf]);

#pragma unroll
        for (int h = 0; h < 2; h++) {
            const __nv_bfloat16(*Wp)[24] = h ? W2s[buf] : W1s[buf];
            unsigned b[2][4];
#pragma unroll
            for (int nt = 0; nt < 2; nt++)
                ldsm4(b[nt][0], b[nt][1], b[nt][2], b[nt][3],
                      &Wp[n0 + 16 * nt + lrow][khalf]);
#pragma unroll
            for (int ni = 0; ni < 4; ni++) {
                int nt = ni >> 1, par = ni & 1;
                unsigned b0 = b[nt][par];
                unsigned b1 = b[nt][par + 2];
#pragma unroll
                for (int mi = 0; mi < 2; mi++) {
                    asm volatile(
                        "mma.sync.aligned.m16n8k16.row.col.f32.bf16.bf16.f32 "
                        "{%0,%1,%2,%3}, {%4,%5,%6,%7}, {%8,%9}, {%0,%1,%2,%3};"
                        : "+f"(c[mi][ni][0]), "+f"(c[mi][ni][1]),
                          "+f"(c[mi][ni][2]), "+f"(c[mi][ni][3])
                        : "r"(a[mi][0]), "r"(a[mi][1]), "r"(a[mi][2]), "r"(a[mi][3]),
                          "r"(b0), "r"(b1));
                }
            }
        }
        __syncthreads();
    }

    // epilogue: scale rows by dinv, store bf16x2
    __nv_bfloat162* bt2 = (__nv_bfloat162*)g_bt;
#pragma unroll
    for (int mi = 0; mi < 2; mi++) {
#pragma unroll
        for (int h = 0; h < 2; h++) {
            int row = row0 + m0 + 16 * mi + grp + 8 * h;
            if (row < NN) {
                float d = g_dinv[row];
#pragma unroll
                for (int ni = 0; ni < 4; ni++) {
                    bt2[(size_t)row * 64 + n0 / 2 + 4 * ni + tig] =
                        __floats2bfloat162_rn(c[mi][ni][2 * h] * d,
                                              c[mi][ni][2 * h + 1] * d);
                }
            }
        }
    }
}

// ---------------- aggregation: one warp per dst node (bf16 gather) --------
// g_hb[i,:] = relu( dinv_i * ( sum_{j in in(i)} u_j + u_i ) + b )
__device__ __forceinline__ float4 bf4(uint2 u) {
    float2 lo = __bfloat1622float2(*(__nv_bfloat162*)&u.x);
    float2 hi = __bfloat1622float2(*(__nv_bfloat162*)&u.y);
    return make_float4(lo.x, lo.y, hi.x, hi.y);
}

__global__ void __launch_bounds__(256) k_agg(const float* __restrict__ bias, int dorelu) {
    int gw = (blockIdx.x * blockDim.x + threadIdx.x) >> 5;
    int lane = threadIdx.x & 31;
    if (gw >= NN) return;

    const uint2* tv = (const uint2*)g_bt;
    float4 acc = bf4(tv[(size_t)gw * 32 + lane]);   // self term u_i

    int e = g_off[gw];
    int end = e + g_cnt[gw];
    for (; e + 8 <= end; e += 8) {
        int j[8];
#pragma unroll
        for (int t = 0; t < 8; t++) j[t] = g_csr[e + t];
        float4 r[8];
#pragma unroll
        for (int t = 0; t < 8; t++) r[t] = bf4(tv[(size_t)j[t] * 32 + lane]);
#pragma unroll
        for (int t = 0; t < 8; t++) {
            acc.x += r[t].x; acc.y += r[t].y;
            acc.z += r[t].z; acc.w += r[t].w;
        }
    }
    for (; e < end; e++) {
        float4 r = bf4(tv[(size_t)g_csr[e] * 32 + lane]);
        acc.x += r.x; acc.y += r.y; acc.z += r.z; acc.w += r.w;
    }

    float di = g_dinv[gw];
    float4 b = ((const float4*)bias)[lane];
    float ox = di * acc.x + b.x;
    float oy = di * acc.y + b.y;
    float oz = di * acc.z + b.z;
    float ow = di * acc.w + b.w;
    if (dorelu) {
        ox = fmaxf(ox, 0.f); oy = fmaxf(oy, 0.f);
        oz = fmaxf(oz, 0.f); ow = fmaxf(ow, 0.f);
    }
    __nv_bfloat162 p0 = __floats2bfloat162_rn(ox, oy);
    __nv_bfloat162 p1 = __floats2bfloat162_rn(oz, ow);
    uint2 packed = make_uint2(*(unsigned*)&p0, *(unsigned*)&p1);
    ((uint2*)g_hb)[(size_t)gw * 32 + lane] = packed;
}

// ---------------- final reduction: g_v = sum_i c_i * h2_i -----------------
__global__ void __launch_bounds__(128) k_reduce() {
    int c = threadIdx.x;
    float acc = 0.0f;
    for (int i = blockIdx.x; i < NN; i += gridDim.x)
        acc += g_c[i] * __bfloat162float(g_hb[(size_t)i * 128 + c]);
    atomicAdd(&g_v[c], acc);
}

__global__ void __launch_bounds__(128) k_final(const float* __restrict__ w3,
                                               const float* __restrict__ b3,
                                               float* __restrict__ out) {
    __shared__ float sv[128];
    int t = threadIdx.x;
    sv[t] = g_v[t];
    __syncthreads();
    float acc = 0.0f;
#pragma unroll 8
    for (int d = 0; d < 128; d++) acc += sv[d] * w3[d * 128 + t];
    out[t] = acc * (1.0f / (float)NN) + b3[t];
}

// ---------------- launch ----------------
// Fork-join: side stream runs k_prep immediately and k_gemm<1> after dinv,
// overlapping the CSR build on the main stream. Event record/wait is the
// capture-legal fork/join mechanism (no sync, no device allocation).
extern "C" void kernel_launch(void* const* d_in, const int* in_sizes, int n_in,
                              void* d_out, int out_size) {
    const float* x  = (const float*)d_in[0];
    const int*   ei = (const int*)d_in[1];
    const float* w1 = (const float*)d_in[2];
    const float* b1 = (const float*)d_in[3];
    const float* w2 = (const float*)d_in[4];
    const float* b2 = (const float*)d_in[5];
    const float* w3 = (const float*)d_in[6];
    const float* b3 = (const float*)d_in[7];
    float* out = (float*)d_out;

    int nThreads = 256;
    int gN = (NN + nThreads - 1) / nThreads;
    int gE = (NE + nThreads - 1) / nThreads;
    int gGemm = (NN + 127) / 128;
    int gAgg = (NN * 32 + nThreads - 1) / nThreads;

    cudaStream_t s2;
    cudaStreamCreate(&s2);
    cudaEvent_t evZ, evA, evB;
    cudaEventCreateWithFlags(&evZ, cudaEventDisableTiming);
    cudaEventCreateWithFlags(&evA, cudaEventDisableTiming);
    cudaEventCreateWithFlags(&evB, cudaEventDisableTiming);

    // fork: side stream becomes capture-associated via evZ
    cudaEventRecord(evZ, 0);
    cudaStreamWaitEvent(s2, evZ, 0);
    k_prep<<<gN, nThreads, 0, s2>>>(w1, w2, x);     // side: W split + x->bf16

    k_zero<<<gN, nThreads>>>();                     // main: zero cnt/s/v
    k_count<<<gE, nThreads>>>(ei);
    k_dinv<<<gN, nThreads>>>();
    cudaEventRecord(evA, 0);                        // dinv ready
    cudaStreamWaitEvent(s2, evA, 0);
    k_gemm<1><<<gGemm, 512, 0, s2>>>();             // side: layer-1 GEMM

    k_scan1<<<NB, 1024>>>();                        // main: CSR build
    k_scan2<<<1, 128>>>();
    k_scan3<<<gN, nThreads>>>();
    k_fill<<<gE, nThreads>>>(ei);
    k_coef<<<gN, nThreads>>>();

    // join: agg1 needs CSR (main) + gemm1 (side)
    cudaEventRecord(evB, s2);
    cudaStreamWaitEvent(0, evB, 0);

    k_agg<<<gAgg, 256>>>(b1, 1);
    k_gemm<0><<<gGemm, 512>>>();
    k_agg<<<gAgg, 256>>>(b2, 1);
    k_reduce<<<512, 128>>>();
    k_final<<<1, 128>>>(w3, b3, out);
    // streams/events intentionally not destroyed: destroying a stream that
    // participated in an active capture invalidates the capture. Host-side
    // handles only; no device memory involved.
}